// round 17
// baseline (speedup 1.0000x reference)
#include <cuda_runtime.h>
#include <math.h>

#define BATCH 16
#define NPTS  2048
#define KNN   10

__device__ float g_loss[BATCH * NPTS];
__device__ float g_blockmin[BATCH * 8];   // plain stores each run; no init needed

// Packed f32x2 helpers (per-lane IEEE fp32, identical rounding to scalar ops)
#define PACK2(out, lo, hi)  asm("mov.b64 %0, {%1, %2};" : "=l"(out) : "f"(lo), "f"(hi))
#define UNPACK2(lo, hi, in) asm("mov.b64 {%0, %1}, %2;" : "=f"(lo), "=f"(hi) : "l"(in))
#define MUL2(out, a, b)     asm("mul.rn.f32x2 %0, %1, %2;" : "=l"(out) : "l"(a), "l"(b))
#define ADD2(out, a, b)     asm("add.rn.f32x2 %0, %1, %2;" : "=l"(out) : "l"(a), "l"(b))
#define FMA2(out, a, b, c)  asm("fma.rn.f32x2 %0, %1, %2, %3;" : "=l"(out) : "l"(a), "l"(b), "l"(c))
// (key_bits, idx) -> u64: low word = idx, high word = key bits
#define PACKKI(out, idx, bits) asm("mov.b64 %0, {%1, %2};" : "=l"(out) : "r"(idx), "r"(bits))

typedef unsigned long long u64;

__device__ __forceinline__ u64 umin64(u64 a, u64 b) { return a < b ? a : b; }
__device__ __forceinline__ u64 umax64(u64 a, u64 b) { return a > b ? a : b; }

__device__ __forceinline__ void sort3(float& a, float& b, float& c) {
    float lo = fminf(a, b), hi = fmaxf(a, b);
    float l0 = fminf(lo, c);
    float l2 = fmaxf(hi, c);
    float l1 = fmaxf(lo, fminf(hi, c));
    a = l0; b = l1; c = l2;
}

// keys for candidate pair (2u, 2u+1): key = ((sqn + sq_m) - 2*dot) + 1e-7,
// dot = x*cx fma y*cy fma z*cz — identical rounding to the verified scalar.
__device__ __forceinline__ void keys2(const float4 xy, const float4 zw,
                                      u64 xn2, u64 yn2, u64 zn2, u64 sqn2,
                                      u64 neg2, u64 eps2,
                                      float& k0, float& k1) {
    u64 cx2, cy2, cz2, cw2, t, s, d, k;
    PACK2(cx2, xy.x, xy.y); PACK2(cy2, xy.z, xy.w);
    PACK2(cz2, zw.x, zw.y); PACK2(cw2, zw.z, zw.w);
    MUL2(t, xn2, cx2);
    FMA2(t, yn2, cy2, t);
    FMA2(t, zn2, cz2, t);          // dot
    ADD2(s, sqn2, cw2);            // sqn + sq_m
    FMA2(d, t, neg2, s);           // d2 = s - 2*dot (one rounding, == scalar)
    ADD2(k, d, eps2);              // key = d2 + 1e-7
    UNPACK2(k0, k1, k);
}

// Dynamic smem layout
#define SM_PXY   0                       // 1024 float4  (16 KB)
#define SM_PZW   16384                   // 1024 float4  (16 KB)
#define SM_KBUF  32768                   // 256*10 u64   (20 KB)  merge buffer
#define SM_FBUF  53248                   // 256*10 float (10 KB)  loss merge buffer
#define SM_TOTAL 63488

__global__ __launch_bounds__(512) void knn_loss_kernel(const float* __restrict__ src,
                                                       const float* __restrict__ tgt) {
    extern __shared__ unsigned char smem[];
    float4* pxy  = (float4*)(smem + SM_PXY);   // (x0,x1,y0,y1) per candidate pair
    float4* pzw  = (float4*)(smem + SM_PZW);   // (z0,z1,sq0,sq1)
    u64*    kb64 = (u64*)(smem + SM_KBUF);
    float*  fbuf = (float*)(smem + SM_FBUF);
    __shared__ float wmin[16];

    const int b     = blockIdx.x >> 3;
    const int chunk = blockIdx.x & 7;
    const int tid   = threadIdx.x;
    const int q     = tid & 255;          // query slot within chunk
    const int half  = tid >> 8;           // 0: candidates [0,1024), 1: [1024,2048)
    const int n     = chunk * 256 + q;

    // ---- Fused prep: load src pairs straight from global, compute |p|^2.
    const float* sb = src + b * 3 * NPTS;
    const float* tb = tgt + b * 3 * NPTS;
    for (int i = tid; i < NPTS / 2; i += 512) {
        float2 xx = ((const float2*)sb)[i];
        float2 yy = ((const float2*)(sb + NPTS))[i];
        float2 zz = ((const float2*)(sb + 2 * NPTS))[i];
        float q0 = xx.x * xx.x + yy.x * yy.x + zz.x * zz.x;   // same expr as verified prep
        float q1 = xx.y * xx.y + yy.y * yy.y + zz.y * zz.y;
        pxy[i] = make_float4(xx.x, xx.y, yy.x, yy.y);
        pzw[i] = make_float4(zz.x, zz.y, q0, q1);
    }
    __syncthreads();

    const float FINF = __int_as_float(0x7f800000);

    // Own point from smem pair (parity select)
    const float4 pa = pxy[n >> 1];
    const float4 pc = pzw[n >> 1];
    const int par = n & 1;
    const float xn  = par ? pa.y : pa.x;
    const float yn  = par ? pa.w : pa.z;
    const float zn  = par ? pc.y : pc.x;
    const float sqn = par ? pc.w : pc.z;

    u64 xn2, yn2, zn2, sqn2, neg2, eps2;
    PACK2(xn2, xn, xn); PACK2(yn2, yn, yn);
    PACK2(zn2, zn, zn); PACK2(sqn2, sqn, sqn);
    { float m2 = -2.0f, ep = 1e-7f; PACK2(neg2, m2, m2); PACK2(eps2, ep, ep); }

    const int mlo = half * (NPTS / 2);
    const int mhi = mlo + NPTS / 2;

    // ---- Single pass (per half): 10 smallest (key, idx) as u64s.
    // u64 = {idx lo, key_bits hi}; keys positive (or masked to +inf) so
    // unsigned u64 order == (key asc, idx asc) == top_k's tie-break exactly.
    // Masked candidates (key<0.1 -> INF bits) rank above every valid key, so
    // the final 10-smallest set == reference's where->top_k selection.
    u64 kb[KNN];
#pragma unroll
    for (int i = 0; i < KNN; i++) kb[i] = ~0ULL;
    u64 th = ~0ULL;

    for (int m0 = mlo; m0 < mhi; m0 += 8) {
        float key[8];
#pragma unroll
        for (int up = 0; up < 4; up++)
            keys2(pxy[(m0 >> 1) + up], pzw[(m0 >> 1) + up],
                  xn2, yn2, zn2, sqn2, neg2, eps2, key[2 * up], key[2 * up + 1]);
#pragma unroll
        for (int u = 0; u < 8; u++) {
            float km = (key[u] >= 0.1f) ? key[u] : FINF;   // ref's mask
            u64 c;
            PACKKI(c, (unsigned)(m0 + u), (unsigned)__float_as_uint(km));
            if (c < th) {
                u64 nk[KNN];
                nk[0] = umin64(kb[0], c);
#pragma unroll
                for (int s = 1; s < KNN; s++) nk[s] = umin64(kb[s], umax64(kb[s - 1], c));
#pragma unroll
                for (int s = 0; s < KNN; s++) kb[s] = nk[s];
                th = kb[KNN - 1];
            }
        }
    }

    // ---- Merge halves: half1 publishes, half0 merges, publishes final.
    if (half) {
#pragma unroll
        for (int s = 0; s < KNN; s++) kb64[q * KNN + s] = kb[s];
    }
    __syncthreads();
    if (!half) {
#pragma unroll
        for (int s = 0; s < KNN; s++) {
            u64 c = kb64[q * KNN + s];
            u64 nk[KNN];
            nk[0] = umin64(kb[0], c);
#pragma unroll
            for (int t2 = 1; t2 < KNN; t2++) nk[t2] = umin64(kb[t2], umax64(kb[t2 - 1], c));
#pragma unroll
            for (int t2 = 0; t2 < KNN; t2++) kb[t2] = nk[t2];
        }
    }
    __syncthreads();
    if (!half) {
#pragma unroll
        for (int s = 0; s < KNN; s++) kb64[q * KNN + s] = kb[s];
    }
    __syncthreads();

    // Final neighbor indices (key-ordered; downstream is multiset-invariant).
    int ib[KNN];
#pragma unroll
    for (int s = 0; s < KNN; s++) ib[s] = (int)(unsigned)kb64[q * KNN + s];

    // ---- Phase 2: gather 10 neighbors — src from smem pairs, tgt from global.
    float nsx[KNN], nsy[KNN], nsz[KNN], ntx[KNN], nty[KNN], ntz[KNN];
#pragma unroll
    for (int i = 0; i < KNN; i++) {
        const int m = ib[i];
        const float4 ca = pxy[m >> 1];
        const float4 cc = pzw[m >> 1];
        const int mp = m & 1;
        nsx[i] = mp ? ca.y : ca.x;
        nsy[i] = mp ? ca.w : ca.z;
        nsz[i] = mp ? cc.y : cc.x;
        ntx[i] = tb[m];
        nty[i] = tb[NPTS + m];
        ntz[i] = tb[2 * NPTS + m];
    }
    const float xtn = tb[n], ytn = tb[NPTS + n], ztn = tb[2 * NPTS + n];

    float ds0[KNN], dt0[KNN];
#pragma unroll
    for (int i = 0; i < KNN; i++) {
        float dx = xn - nsx[i], dy = yn - nsy[i], dz = zn - nsz[i];
        ds0[i] = dx * dx + dy * dy + dz * dz;
        float ex = xtn - ntx[i], ey = ytn - nty[i], ez = ztn - ntz[i];
        dt0[i] = ex * ex + ey * ey + ez * ez;
    }

    // ---- Phase 3: 45 pairs split 23/22 across the halves; 10-smallest via
    // lattice (kept sorted ascending). Loss multiset -> split is result-exact.
    float lb[KNN];
#pragma unroll
    for (int i = 0; i < KNN; i++) lb[i] = FINF;

    int p = 0;
#pragma unroll
    for (int i = 0; i < KNN; i++) {
#pragma unroll
        for (int j = i + 1; j < KNN; j++) {
            if ((half == 0) ? (p < 23) : (p >= 23)) {
                float dx = nsx[i] - nsx[j], dy = nsy[i] - nsy[j], dz = nsz[i] - nsz[j];
                float bs = dx * dx + dy * dy + dz * dz;
                float l0 = ds0[i], l1 = bs, l2 = ds0[j];
                sort3(l0, l1, l2);

                float ex = ntx[i] - ntx[j], ey = nty[i] - nty[j], ez = ntz[i] - ntz[j];
                float bt = ex * ex + ey * ey + ez * ez;
                float m0 = dt0[i], m1 = bt, m2 = dt0[j];
                sort3(m0, m1, m2);
                m0 += 1e-6f; m1 += 1e-6f; m2 += 1e-6f;   // length_tgt + EPS

                float e0 = l0 - m0, e1 = l1 - m1, e2 = l2 - m2;
                float num = e0 * e0 + e1 * e1 + e2 * e2;
                float s0 = l0 + m0, s1 = l1 + m1, s2 = l2 + m2;
                float den = s0 * s0 + s1 * s1 + s2 * s2;
                float ck = num / den;

                float nl[KNN];
                nl[0] = fminf(lb[0], ck);
#pragma unroll
                for (int s = 1; s < KNN; s++) nl[s] = fminf(lb[s], fmaxf(lb[s - 1], ck));
#pragma unroll
                for (int s = 0; s < KNN; s++) lb[s] = nl[s];
            }
            p++;
        }
    }

    if (half) {
#pragma unroll
        for (int s = 0; s < KNN; s++) fbuf[q * KNN + s] = lb[s];
    }
    __syncthreads();

    float mloss = 0.0f;
    if (!half) {
#pragma unroll
        for (int s = 0; s < KNN; s++) {
            float c = fbuf[q * KNN + s];
            float nl[KNN];
            nl[0] = fminf(lb[0], c);
#pragma unroll
            for (int t2 = 1; t2 < KNN; t2++) nl[t2] = fminf(lb[t2], fmaxf(lb[t2 - 1], c));
#pragma unroll
            for (int t2 = 0; t2 < KNN; t2++) lb[t2] = nl[t2];
        }
        float acc = 0.0f;
#pragma unroll
        for (int i = 0; i < KNN; i++) acc += sqrtf(lb[i] + 1e-6f);   // ascending order
        mloss = acc / 10.0f;
        g_loss[b * NPTS + n] = mloss;
    }

    // ---- Block min -> plain store (no atomics, no init kernel needed)
    float v = (!half) ? mloss : FINF;
#pragma unroll
    for (int o = 16; o > 0; o >>= 1) v = fminf(v, __shfl_xor_sync(0xffffffffu, v, o));
    if ((tid & 31) == 0) wmin[tid >> 5] = v;
    __syncthreads();
    if (tid == 0) {
        float bm = wmin[0];
#pragma unroll
        for (int w = 1; w < 16; w++) bm = fminf(bm, wmin[w]);
        g_blockmin[blockIdx.x] = bm;
    }
}

__global__ __launch_bounds__(256) void weight_kernel(float* __restrict__ out) {
    const int b = blockIdx.x >> 3;
    const int i = (blockIdx.x & 7) * 256 + threadIdx.x;
    float minl = g_blockmin[b * 8];
#pragma unroll
    for (int j = 1; j < 8; j++) minl = fminf(minl, g_blockmin[b * 8 + j]);
    float t = g_loss[b * NPTS + i] - minl;
    float w = 2.0f / (1.0f + expf(30.0f * t));   // 2*sigmoid(-30*t)
    out[b * NPTS + i] = (w > 0.6f) ? 1.0f : 0.0f;
}

extern "C" void kernel_launch(void* const* d_in, const int* in_sizes, int n_in,
                              void* d_out, int out_size) {
    const float* src = (const float*)d_in[0];
    const float* tgt = (const float*)d_in[1];
    float* out = (float*)d_out;

    cudaFuncSetAttribute(knn_loss_kernel, cudaFuncAttributeMaxDynamicSharedMemorySize, SM_TOTAL);

    knn_loss_kernel<<<BATCH * 8, 512, SM_TOTAL>>>(src, tgt);
    weight_kernel<<<BATCH * 8, 256>>>(out);
}